// round 1
// baseline (speedup 1.0000x reference)
#include <cuda_runtime.h>

#define NNODES 40000
#define NEDGES 640000
#define TE     (NEDGES + NNODES)
#define CH     128
#define BN_EPS 1e-5f
#define NEG    0.2f

// ---------------- scratch (device globals: no allocation allowed) ----------
__device__ __align__(16) float g_xl[NNODES * CH];
__device__ __align__(16) float g_xr[NNODES * CH];
__device__ __align__(16) float g_h [NNODES * CH];
__device__ __align__(16) int   g_deg[NNODES];
__device__ __align__(16) int   g_rowstart[NNODES + 4]; // +pad for int4 stores
__device__ __align__(16) int   g_cursor[NNODES];
__device__             int     g_csr[TE];

// ---------------- CSR build --------------------------------------------------
__global__ void k_init_deg() {
    int i = blockIdx.x * blockDim.x + threadIdx.x;
    if (i < NNODES) g_deg[i] = 1;  // self loop
}

__global__ void k_hist(const int* __restrict__ dst) {
    int i = blockIdx.x * blockDim.x + threadIdx.x;
    if (i < NEDGES) atomicAdd(&g_deg[dst[i]], 1);
}

// single-block chunked exclusive scan, 4 elements/thread per chunk
__global__ void k_scan() {
    __shared__ int sm[1024];
    int tid = threadIdx.x;
    int carry = 0;
    for (int base = 0; base < NNODES; base += 4096) {
        int idx = base + tid * 4;
        int4 v = make_int4(0, 0, 0, 0);
        if (idx < NNODES) v = *(const int4*)&g_deg[idx];
        int l0 = v.x;
        int l1 = l0 + v.y;
        int l2 = l1 + v.z;
        int l3 = l2 + v.w;
        sm[tid] = l3;
        __syncthreads();
        int val = l3;
        #pragma unroll
        for (int off = 1; off < 1024; off <<= 1) {
            int t = (tid >= off) ? sm[tid - off] : 0;
            __syncthreads();
            val += t;
            sm[tid] = val;
            __syncthreads();
        }
        int excl = val - l3 + carry;  // exclusive prefix for this thread's 4
        if (idx < NNODES) {
            int4 r;
            r.x = excl;
            r.y = excl + l0;
            r.z = excl + l1;
            r.w = excl + l2;
            *(int4*)&g_rowstart[idx] = r;
            *(int4*)&g_cursor[idx]   = r;
        }
        carry += sm[1023];
        __syncthreads();
    }
    if (tid == 0) g_rowstart[NNODES] = carry;  // == TE
}

__global__ void k_scatter(const int* __restrict__ ei) {
    int i = blockIdx.x * blockDim.x + threadIdx.x;
    if (i < NEDGES) {
        int s = ei[i];
        int d = ei[NEDGES + i];
        int pos = atomicAdd(&g_cursor[d], 1);
        g_csr[pos] = s;
    } else if (i < TE) {
        int node = i - NEDGES;
        int pos = atomicAdd(&g_cursor[node], 1);
        g_csr[pos] = node;  // self loop
    }
}

// ---------------- SGEMM: C[M,128] = A[M,128] @ B[128,128] + bias (opt relu) --
// asel: 0 -> Aext, 1 -> g_h
// csel: 0 -> g_xl, 1 -> g_xr
__global__ __launch_bounds__(256) void k_sgemm(
    const float* __restrict__ Aext, const float* __restrict__ B,
    const float* __restrict__ bias, int asel, int csel, int M, int relu)
{
    const float* A = asel ? g_h : Aext;
    float* C = csel ? g_xr : g_xl;

    __shared__ float As[16][128];  // transposed: As[k][m]
    __shared__ float Bs[16][128];

    int row0 = blockIdx.x * 128;
    int tid = threadIdx.x;
    int ty = tid >> 4;   // 0..15
    int tx = tid & 15;   // 0..15

    float acc[8][8];
    #pragma unroll
    for (int i = 0; i < 8; i++)
        #pragma unroll
        for (int j = 0; j < 8; j++) acc[i][j] = 0.f;

    for (int k0 = 0; k0 < 128; k0 += 16) {
        // load A tile (128 x 16) transposed into As[k][m]
        #pragma unroll
        for (int l = 0; l < 2; l++) {
            int q = tid + l * 256;      // 0..511 float4s
            int r = q >> 2;             // row in tile 0..127
            int kc = (q & 3) << 2;      // k within tile 0,4,8,12
            int gr = row0 + r;
            float4 v = make_float4(0.f, 0.f, 0.f, 0.f);
            if (gr < M) v = *(const float4*)&A[gr * 128 + k0 + kc];
            As[kc + 0][r] = v.x;
            As[kc + 1][r] = v.y;
            As[kc + 2][r] = v.z;
            As[kc + 3][r] = v.w;
        }
        // load B tile (16 x 128)
        #pragma unroll
        for (int l = 0; l < 2; l++) {
            int q = tid + l * 256;
            int kr = q >> 5;            // 0..15
            int c = (q & 31) << 2;      // 0..124
            *(float4*)&Bs[kr][c] = *(const float4*)&B[(k0 + kr) * 128 + c];
        }
        __syncthreads();

        #pragma unroll
        for (int k = 0; k < 16; k++) {
            float4 a0 = *(const float4*)&As[k][ty * 8];
            float4 a1 = *(const float4*)&As[k][ty * 8 + 4];
            float4 b0 = *(const float4*)&Bs[k][tx * 8];
            float4 b1 = *(const float4*)&Bs[k][tx * 8 + 4];
            float a[8] = {a0.x, a0.y, a0.z, a0.w, a1.x, a1.y, a1.z, a1.w};
            float b[8] = {b0.x, b0.y, b0.z, b0.w, b1.x, b1.y, b1.z, b1.w};
            #pragma unroll
            for (int i = 0; i < 8; i++)
                #pragma unroll
                for (int j = 0; j < 8; j++)
                    acc[i][j] = fmaf(a[i], b[j], acc[i][j]);
        }
        __syncthreads();
    }

    // epilogue
    float4 bb0 = *(const float4*)&bias[tx * 8];
    float4 bb1 = *(const float4*)&bias[tx * 8 + 4];
    float bb[8] = {bb0.x, bb0.y, bb0.z, bb0.w, bb1.x, bb1.y, bb1.z, bb1.w};
    #pragma unroll
    for (int i = 0; i < 8; i++) {
        int gr = row0 + ty * 8 + i;
        if (gr < M) {
            float o[8];
            #pragma unroll
            for (int j = 0; j < 8; j++) {
                float v = acc[i][j] + bb[j];
                if (relu) v = fmaxf(v, 0.f);
                o[j] = v;
            }
            *(float4*)&C[gr * 128 + tx * 8]     = make_float4(o[0], o[1], o[2], o[3]);
            *(float4*)&C[gr * 128 + tx * 8 + 4] = make_float4(o[4], o[5], o[6], o[7]);
        }
    }
}

// ---------------- GAT edge aggregation: one warp per destination node --------
// online softmax over incoming edges; fused bias + BN(eval) + ReLU epilogue
__global__ __launch_bounds__(256) void k_gat(
    const float* __restrict__ att, const float* __restrict__ bias,
    const float* __restrict__ g, const float* __restrict__ be,
    const float* __restrict__ rm, const float* __restrict__ rv)
{
    int w = (blockIdx.x * blockDim.x + threadIdx.x) >> 5;
    int lane = threadIdx.x & 31;
    if (w >= NNODES) return;
    int c0 = lane * 4;

    float4 xr4 = *(const float4*)&g_xr[w * CH + c0];
    float4 at4 = *(const float4*)&att[c0];

    int rs = g_rowstart[w];
    int re = g_rowstart[w + 1];

    float mx = __int_as_float(0xff800000);  // -inf
    float ss = 0.f;
    float ax = 0.f, ay = 0.f, az = 0.f, aw = 0.f;

    for (int base = rs; base < re; base += 32) {
        int myidx = base + lane;
        int msrc = (myidx < re) ? g_csr[myidx] : 0;
        int cnt = min(32, re - base);
        for (int t = 0; t < cnt; t++) {
            int sn = __shfl_sync(0xffffffffu, msrc, t);
            float4 xl4 = *(const float4*)&g_xl[sn * CH + c0];
            float tx_ = xl4.x + xr4.x;
            float ty_ = xl4.y + xr4.y;
            float tz_ = xl4.z + xr4.z;
            float tw_ = xl4.w + xr4.w;
            tx_ = fmaxf(tx_, 0.f) + NEG * fminf(tx_, 0.f);
            ty_ = fmaxf(ty_, 0.f) + NEG * fminf(ty_, 0.f);
            tz_ = fmaxf(tz_, 0.f) + NEG * fminf(tz_, 0.f);
            tw_ = fmaxf(tw_, 0.f) + NEG * fminf(tw_, 0.f);
            float part = tx_ * at4.x + ty_ * at4.y + tz_ * at4.z + tw_ * at4.w;
            #pragma unroll
            for (int o = 16; o; o >>= 1)
                part += __shfl_xor_sync(0xffffffffu, part, o);
            // online softmax update
            float nm = fmaxf(mx, part);
            float c = __expf(mx - nm);
            float p = __expf(part - nm);
            ss = ss * c + p;
            ax = fmaf(ax, c, p * xl4.x);
            ay = fmaf(ay, c, p * xl4.y);
            az = fmaf(az, c, p * xl4.z);
            aw = fmaf(aw, c, p * xl4.w);
            mx = nm;
        }
    }

    float inv = 1.f / ss;
    float4 b4  = *(const float4*)&bias[c0];
    float4 g4  = *(const float4*)&g[c0];
    float4 be4 = *(const float4*)&be[c0];
    float4 rm4 = *(const float4*)&rm[c0];
    float4 rv4 = *(const float4*)&rv[c0];

    float4 o;
    {
        float v = ax * inv + b4.x;
        float sc = g4.x * rsqrtf(rv4.x + BN_EPS);
        o.x = fmaxf((v - rm4.x) * sc + be4.x, 0.f);
    }
    {
        float v = ay * inv + b4.y;
        float sc = g4.y * rsqrtf(rv4.y + BN_EPS);
        o.y = fmaxf((v - rm4.y) * sc + be4.y, 0.f);
    }
    {
        float v = az * inv + b4.z;
        float sc = g4.z * rsqrtf(rv4.z + BN_EPS);
        o.z = fmaxf((v - rm4.z) * sc + be4.z, 0.f);
    }
    {
        float v = aw * inv + b4.w;
        float sc = g4.w * rsqrtf(rv4.w + BN_EPS);
        o.w = fmaxf((v - rm4.w) * sc + be4.w, 0.f);
    }
    *(float4*)&g_h[w * CH + c0] = o;
}

// ---------------- final tiny GEMM: out[M,2] = X[M,128] @ W[128,2] + b --------
__global__ void k_lin2(const float* __restrict__ W, const float* __restrict__ b,
                       float* __restrict__ out)
{
    int w = (blockIdx.x * blockDim.x + threadIdx.x) >> 5;
    int lane = threadIdx.x & 31;
    if (w >= NNODES) return;
    float4 v  = *(const float4*)&g_xl[w * CH + lane * 4];
    float4 w0 = *(const float4*)&W[lane * 8];      // {W[k0][0],W[k0][1],W[k1][0],W[k1][1]}
    float4 w1 = *(const float4*)&W[lane * 8 + 4];  // {W[k2][0],W[k2][1],W[k3][0],W[k3][1]}
    float s0 = v.x * w0.x + v.y * w0.z + v.z * w1.x + v.w * w1.z;
    float s1 = v.x * w0.y + v.y * w0.w + v.z * w1.y + v.w * w1.w;
    #pragma unroll
    for (int o = 16; o; o >>= 1) {
        s0 += __shfl_xor_sync(0xffffffffu, s0, o);
        s1 += __shfl_xor_sync(0xffffffffu, s1, o);
    }
    if (lane == 0) {
        out[w * 2 + 0] = s0 + b[0];
        out[w * 2 + 1] = s1 + b[1];
    }
}

// ---------------- launch -----------------------------------------------------
extern "C" void kernel_launch(void* const* d_in, const int* in_sizes, int n_in,
                              void* d_out, int out_size)
{
    const float* x     = (const float*)d_in[0];
    const int*   ei    = (const int*)  d_in[1];
    const float* Wl0   = (const float*)d_in[2];
    const float* bl0   = (const float*)d_in[3];
    const float* Wr0   = (const float*)d_in[4];
    const float* br0   = (const float*)d_in[5];
    const float* att0  = (const float*)d_in[6];
    const float* bias0 = (const float*)d_in[7];
    const float* g0    = (const float*)d_in[8];
    const float* be0   = (const float*)d_in[9];
    const float* rm0   = (const float*)d_in[10];
    const float* rv0   = (const float*)d_in[11];
    const float* Wl1   = (const float*)d_in[12];
    const float* bl1   = (const float*)d_in[13];
    const float* Wr1   = (const float*)d_in[14];
    const float* br1   = (const float*)d_in[15];
    const float* att1  = (const float*)d_in[16];
    const float* bias1 = (const float*)d_in[17];
    const float* g1    = (const float*)d_in[18];
    const float* be1   = (const float*)d_in[19];
    const float* rm1   = (const float*)d_in[20];
    const float* rv1   = (const float*)d_in[21];
    const float* Wlin1 = (const float*)d_in[22];
    const float* blin1 = (const float*)d_in[23];
    const float* Wlin2 = (const float*)d_in[24];
    const float* blin2 = (const float*)d_in[25];
    float* out = (float*)d_out;

    const int GEMM_BLOCKS = (NNODES + 127) / 128;      // 313
    const int GAT_BLOCKS  = (NNODES * 32 + 255) / 256; // 5000

    // CSR build (interleaved with layer-0 GEMMs; stream order gives deps)
    k_init_deg<<<(NNODES + 255) / 256, 256>>>();
    k_hist<<<(NEDGES + 255) / 256, 256>>>(ei + NEDGES);
    k_sgemm<<<GEMM_BLOCKS, 256>>>(x, Wl0, bl0, /*asel=*/0, /*csel=*/0, NNODES, 0); // xl0
    k_sgemm<<<GEMM_BLOCKS, 256>>>(x, Wr0, br0, /*asel=*/0, /*csel=*/1, NNODES, 0); // xr0
    k_scan<<<1, 1024>>>();
    k_scatter<<<(TE + 255) / 256, 256>>>(ei);

    // layer 0
    k_gat<<<GAT_BLOCKS, 256>>>(att0, bias0, g0, be0, rm0, rv0);          // -> g_h

    // layer 1
    k_sgemm<<<GEMM_BLOCKS, 256>>>(nullptr, Wl1, bl1, 1, 0, NNODES, 0);   // xl1 = h0@Wl1
    k_sgemm<<<GEMM_BLOCKS, 256>>>(nullptr, Wr1, br1, 1, 1, NNODES, 0);   // xr1 = h0@Wr1
    k_gat<<<GAT_BLOCKS, 256>>>(att1, bias1, g1, be1, rm1, rv1);          // -> g_h

    // MLP head
    k_sgemm<<<GEMM_BLOCKS, 256>>>(nullptr, Wlin1, blin1, 1, 0, NNODES, 1); // g_xl = relu(h1@Wlin1+b)
    k_lin2<<<GAT_BLOCKS, 256>>>(Wlin2, blin2, out);
}

// round 2
// speedup vs baseline: 1.5941x; 1.5941x over previous
#include <cuda_runtime.h>

#define NNODES 40000
#define NEDGES 640000
#define TE     (NEDGES + NNODES)
#define CH     128
#define BN_EPS 1e-5f
#define NEG    0.2f

// ---------------- scratch (device globals: no allocation allowed) ----------
__device__ __align__(16) float g_xl[NNODES * CH];
__device__ __align__(16) float g_xr[NNODES * CH];
__device__ __align__(16) float g_h [NNODES * CH];
__device__ __align__(16) int   g_deg[NNODES];
__device__ __align__(16) int   g_rowstart[NNODES + 4];
__device__ __align__(16) int   g_cursor[NNODES];
__device__             int     g_csr[TE];

// ---------------- CSR build --------------------------------------------------
__global__ void k_init_deg() {
    int i = blockIdx.x * blockDim.x + threadIdx.x;
    if (i < NNODES) g_deg[i] = 1;  // self loop
}

__global__ void k_hist(const int* __restrict__ dst) {
    int i = blockIdx.x * blockDim.x + threadIdx.x;
    if (i < NEDGES) atomicAdd(&g_deg[dst[i]], 1);
}

__global__ void k_scan() {
    __shared__ int sm[1024];
    int tid = threadIdx.x;
    int carry = 0;
    for (int base = 0; base < NNODES; base += 4096) {
        int idx = base + tid * 4;
        int4 v = make_int4(0, 0, 0, 0);
        if (idx < NNODES) v = *(const int4*)&g_deg[idx];
        int l0 = v.x;
        int l1 = l0 + v.y;
        int l2 = l1 + v.z;
        int l3 = l2 + v.w;
        sm[tid] = l3;
        __syncthreads();
        int val = l3;
        #pragma unroll
        for (int off = 1; off < 1024; off <<= 1) {
            int t = (tid >= off) ? sm[tid - off] : 0;
            __syncthreads();
            val += t;
            sm[tid] = val;
            __syncthreads();
        }
        int excl = val - l3 + carry;
        if (idx < NNODES) {
            int4 r;
            r.x = excl;
            r.y = excl + l0;
            r.z = excl + l1;
            r.w = excl + l2;
            *(int4*)&g_rowstart[idx] = r;
            *(int4*)&g_cursor[idx]   = r;
        }
        carry += sm[1023];
        __syncthreads();
    }
    if (tid == 0) g_rowstart[NNODES] = carry;
}

__global__ void k_scatter(const int* __restrict__ ei) {
    int i = blockIdx.x * blockDim.x + threadIdx.x;
    if (i < NEDGES) {
        int s = ei[i];
        int d = ei[NEDGES + i];
        int pos = atomicAdd(&g_cursor[d], 1);
        g_csr[pos] = s;
    } else if (i < TE) {
        int node = i - NEDGES;
        int pos = atomicAdd(&g_cursor[node], 1);
        g_csr[pos] = node;
    }
}

// ---------------- TF32 tensor-core GEMM --------------------------------------
// C[M,128] = A[M,128] @ B[128,128] + bias.  dual: also C2 = A @ B2 + bias2.
// Outputs fixed: C1 = g_xl, C2 = g_xr.  asel: 0 -> Aext, 1 -> g_h.
// Shared: sA [128][132] (tf32 bits), sB0/sB1 [128][136].
#define SA_STRIDE 132
#define SB_STRIDE 136
#define SMEM_UINTS (128 * SA_STRIDE + 2 * 128 * SB_STRIDE)
#define SMEM_BYTES (SMEM_UINTS * 4)

__device__ __forceinline__ unsigned f2tf(float x) {
    unsigned r;
    asm("cvt.rna.tf32.f32 %0, %1;" : "=r"(r) : "f"(x));
    return r;
}

__device__ __forceinline__ void mma_tf32(float* c, const unsigned* a,
                                         unsigned b0, unsigned b1) {
    asm volatile(
        "mma.sync.aligned.m16n8k8.row.col.f32.tf32.tf32.f32 "
        "{%0,%1,%2,%3}, {%4,%5,%6,%7}, {%8,%9}, {%0,%1,%2,%3};"
        : "+f"(c[0]), "+f"(c[1]), "+f"(c[2]), "+f"(c[3])
        : "r"(a[0]), "r"(a[1]), "r"(a[2]), "r"(a[3]), "r"(b0), "r"(b1));
}

__global__ __launch_bounds__(256) void k_mm_tc(
    const float* __restrict__ Aext, int asel,
    const float* __restrict__ B1, const float* __restrict__ bias1,
    const float* __restrict__ B2, const float* __restrict__ bias2,
    int dual, int relu, int M)
{
    extern __shared__ unsigned smem[];
    unsigned* sA  = smem;
    unsigned* sB0 = sA + 128 * SA_STRIDE;
    unsigned* sB1 = sB0 + 128 * SB_STRIDE;

    const float* A = asel ? (const float*)g_h : Aext;
    const int tid = threadIdx.x;
    const int wid = tid >> 5, lane = tid & 31;
    const int q = lane & 3, g = lane >> 2;
    const int row0 = blockIdx.x * 128;

    // stage A (tf32), guarded
    #pragma unroll
    for (int l = 0; l < 16; l++) {
        int i = tid + l * 256;
        int r = i >> 5, c = (i & 31) << 2;
        float4 v = make_float4(0.f, 0.f, 0.f, 0.f);
        int gr = row0 + r;
        if (gr < M) v = *(const float4*)&A[gr * 128 + c];
        uint4 t;
        t.x = f2tf(v.x); t.y = f2tf(v.y); t.z = f2tf(v.z); t.w = f2tf(v.w);
        *(uint4*)&sA[r * SA_STRIDE + c] = t;
    }
    // stage B1 (tf32)
    #pragma unroll
    for (int l = 0; l < 16; l++) {
        int i = tid + l * 256;
        int r = i >> 5, c = (i & 31) << 2;
        float4 v = *(const float4*)&B1[r * 128 + c];
        uint4 t;
        t.x = f2tf(v.x); t.y = f2tf(v.y); t.z = f2tf(v.z); t.w = f2tf(v.w);
        *(uint4*)&sB0[r * SB_STRIDE + c] = t;
    }
    if (dual) {
        #pragma unroll
        for (int l = 0; l < 16; l++) {
            int i = tid + l * 256;
            int r = i >> 5, c = (i & 31) << 2;
            float4 v = *(const float4*)&B2[r * 128 + c];
            uint4 t;
            t.x = f2tf(v.x); t.y = f2tf(v.y); t.z = f2tf(v.z); t.w = f2tf(v.w);
            *(uint4*)&sB1[r * SB_STRIDE + c] = t;
        }
    }
    __syncthreads();

    // warp tiling
    int m_tiles, wr, colbase;
    const unsigned* sB;
    const float* bias;
    float* C;
    if (dual) {
        int gm = wid >> 2;
        wr = ((wid >> 1) & 1) * 64;
        colbase = (wid & 1) * 64;
        m_tiles = 4;
        sB = gm ? sB1 : sB0;
        bias = gm ? bias2 : bias1;
        C = gm ? g_xr : g_xl;
    } else {
        wr = (wid >> 1) * 32;
        colbase = (wid & 1) * 64;
        m_tiles = 2;
        sB = sB0;
        bias = bias1;
        C = g_xl;
    }

    float acc[4][8][4];
    #pragma unroll
    for (int mt = 0; mt < 4; mt++)
        #pragma unroll
        for (int nt = 0; nt < 8; nt++)
            #pragma unroll
            for (int j = 0; j < 4; j++) acc[mt][nt][j] = 0.f;

    for (int ks = 0; ks < 16; ks++) {
        int k0 = ks * 8;
        unsigned a[4][4];
        #pragma unroll
        for (int mt = 0; mt < 4; mt++)
            if (mt < m_tiles) {
                int rb = wr + mt * 16;
                a[mt][0] = sA[(rb + g) * SA_STRIDE + k0 + q];
                a[mt][1] = sA[(rb + 8 + g) * SA_STRIDE + k0 + q];
                a[mt][2] = sA[(rb + g) * SA_STRIDE + k0 + q + 4];
                a[mt][3] = sA[(rb + 8 + g) * SA_STRIDE + k0 + q + 4];
            }
        #pragma unroll
        for (int nt = 0; nt < 8; nt++) {
            int cb = colbase + nt * 8 + g;
            unsigned b0 = sB[(k0 + q) * SB_STRIDE + cb];
            unsigned b1 = sB[(k0 + q + 4) * SB_STRIDE + cb];
            #pragma unroll
            for (int mt = 0; mt < 4; mt++)
                if (mt < m_tiles) mma_tf32(acc[mt][nt], a[mt], b0, b1);
        }
    }

    // epilogue: bias (+optional relu), float2 stores
    #pragma unroll
    for (int nt = 0; nt < 8; nt++) {
        int col = colbase + nt * 8 + q * 2;
        float2 bb = *(const float2*)&bias[col];
        #pragma unroll
        for (int mt = 0; mt < 4; mt++)
            if (mt < m_tiles) {
                int r0 = row0 + wr + mt * 16 + g;
                float v0 = acc[mt][nt][0] + bb.x;
                float v1 = acc[mt][nt][1] + bb.y;
                float v2 = acc[mt][nt][2] + bb.x;
                float v3 = acc[mt][nt][3] + bb.y;
                if (relu) {
                    v0 = fmaxf(v0, 0.f); v1 = fmaxf(v1, 0.f);
                    v2 = fmaxf(v2, 0.f); v3 = fmaxf(v3, 0.f);
                }
                if (r0 < M) {
                    float2 s = make_float2(v0, v1);
                    *(float2*)&C[r0 * 128 + col] = s;
                }
                if (r0 + 8 < M) {
                    float2 s = make_float2(v2, v3);
                    *(float2*)&C[(r0 + 8) * 128 + col] = s;
                }
            }
    }
}

// ---------------- GAT edge aggregation: one warp per destination node --------
__global__ __launch_bounds__(256) void k_gat(
    const float* __restrict__ att, const float* __restrict__ bias,
    const float* __restrict__ g, const float* __restrict__ be,
    const float* __restrict__ rm, const float* __restrict__ rv)
{
    int w = (blockIdx.x * blockDim.x + threadIdx.x) >> 5;
    int lane = threadIdx.x & 31;
    if (w >= NNODES) return;
    int c0 = lane * 4;

    float4 xr4 = *(const float4*)&g_xr[w * CH + c0];
    float4 at4 = *(const float4*)&att[c0];

    int rs = g_rowstart[w];
    int re = g_rowstart[w + 1];

    float mx = __int_as_float(0xff800000);
    float ss = 0.f;
    float ax = 0.f, ay = 0.f, az = 0.f, aw = 0.f;

    for (int base = rs; base < re; base += 32) {
        int myidx = base + lane;
        int msrc = (myidx < re) ? g_csr[myidx] : 0;
        int cnt = min(32, re - base);
        for (int t = 0; t < cnt; t++) {
            int sn = __shfl_sync(0xffffffffu, msrc, t);
            float4 xl4 = *(const float4*)&g_xl[sn * CH + c0];
            float tx_ = xl4.x + xr4.x;
            float ty_ = xl4.y + xr4.y;
            float tz_ = xl4.z + xr4.z;
            float tw_ = xl4.w + xr4.w;
            tx_ = fmaxf(tx_, 0.f) + NEG * fminf(tx_, 0.f);
            ty_ = fmaxf(ty_, 0.f) + NEG * fminf(ty_, 0.f);
            tz_ = fmaxf(tz_, 0.f) + NEG * fminf(tz_, 0.f);
            tw_ = fmaxf(tw_, 0.f) + NEG * fminf(tw_, 0.f);
            float part = tx_ * at4.x + ty_ * at4.y + tz_ * at4.z + tw_ * at4.w;
            #pragma unroll
            for (int o = 16; o; o >>= 1)
                part += __shfl_xor_sync(0xffffffffu, part, o);
            float nm = fmaxf(mx, part);
            float c = __expf(mx - nm);
            float p = __expf(part - nm);
            ss = ss * c + p;
            ax = fmaf(ax, c, p * xl4.x);
            ay = fmaf(ay, c, p * xl4.y);
            az = fmaf(az, c, p * xl4.z);
            aw = fmaf(aw, c, p * xl4.w);
            mx = nm;
        }
    }

    float inv = 1.f / ss;
    float4 b4  = *(const float4*)&bias[c0];
    float4 g4  = *(const float4*)&g[c0];
    float4 be4 = *(const float4*)&be[c0];
    float4 rm4 = *(const float4*)&rm[c0];
    float4 rv4 = *(const float4*)&rv[c0];

    float4 o;
    o.x = fmaxf((ax * inv + b4.x - rm4.x) * (g4.x * rsqrtf(rv4.x + BN_EPS)) + be4.x, 0.f);
    o.y = fmaxf((ay * inv + b4.y - rm4.y) * (g4.y * rsqrtf(rv4.y + BN_EPS)) + be4.y, 0.f);
    o.z = fmaxf((az * inv + b4.z - rm4.z) * (g4.z * rsqrtf(rv4.z + BN_EPS)) + be4.z, 0.f);
    o.w = fmaxf((aw * inv + b4.w - rm4.w) * (g4.w * rsqrtf(rv4.w + BN_EPS)) + be4.w, 0.f);
    *(float4*)&g_h[w * CH + c0] = o;
}

// ---------------- final tiny GEMM: out[M,2] = X[M,128] @ W[128,2] + b --------
__global__ void k_lin2(const float* __restrict__ W, const float* __restrict__ b,
                       float* __restrict__ out)
{
    int w = (blockIdx.x * blockDim.x + threadIdx.x) >> 5;
    int lane = threadIdx.x & 31;
    if (w >= NNODES) return;
    float4 v  = *(const float4*)&g_xl[w * CH + lane * 4];
    float4 w0 = *(const float4*)&W[lane * 8];
    float4 w1 = *(const float4*)&W[lane * 8 + 4];
    float s0 = v.x * w0.x + v.y * w0.z + v.z * w1.x + v.w * w1.z;
    float s1 = v.x * w0.y + v.y * w0.w + v.z * w1.y + v.w * w1.w;
    #pragma unroll
    for (int o = 16; o; o >>= 1) {
        s0 += __shfl_xor_sync(0xffffffffu, s0, o);
        s1 += __shfl_xor_sync(0xffffffffu, s1, o);
    }
    if (lane == 0) {
        out[w * 2 + 0] = s0 + b[0];
        out[w * 2 + 1] = s1 + b[1];
    }
}

// ---------------- launch -----------------------------------------------------
extern "C" void kernel_launch(void* const* d_in, const int* in_sizes, int n_in,
                              void* d_out, int out_size)
{
    const float* x     = (const float*)d_in[0];
    const int*   ei    = (const int*)  d_in[1];
    const float* Wl0   = (const float*)d_in[2];
    const float* bl0   = (const float*)d_in[3];
    const float* Wr0   = (const float*)d_in[4];
    const float* br0   = (const float*)d_in[5];
    const float* att0  = (const float*)d_in[6];
    const float* bias0 = (const float*)d_in[7];
    const float* g0    = (const float*)d_in[8];
    const float* be0   = (const float*)d_in[9];
    const float* rm0   = (const float*)d_in[10];
    const float* rv0   = (const float*)d_in[11];
    const float* Wl1   = (const float*)d_in[12];
    const float* bl1   = (const float*)d_in[13];
    const float* Wr1   = (const float*)d_in[14];
    const float* br1   = (const float*)d_in[15];
    const float* att1  = (const float*)d_in[16];
    const float* bias1 = (const float*)d_in[17];
    const float* g1    = (const float*)d_in[18];
    const float* be1   = (const float*)d_in[19];
    const float* rm1   = (const float*)d_in[20];
    const float* rv1   = (const float*)d_in[21];
    const float* Wlin1 = (const float*)d_in[22];
    const float* blin1 = (const float*)d_in[23];
    const float* Wlin2 = (const float*)d_in[24];
    const float* blin2 = (const float*)d_in[25];
    float* out = (float*)d_out;

    cudaFuncSetAttribute(k_mm_tc, cudaFuncAttributeMaxDynamicSharedMemorySize,
                         SMEM_BYTES);

    const int GEMM_BLOCKS = (NNODES + 127) / 128;      // 313
    const int GAT_BLOCKS  = (NNODES * 32 + 255) / 256; // 5000

    k_init_deg<<<(NNODES + 255) / 256, 256>>>();
    k_hist<<<(NEDGES + 255) / 256, 256>>>(ei + NEDGES);
    k_mm_tc<<<GEMM_BLOCKS, 256, SMEM_BYTES>>>(x, 0, Wl0, bl0, Wr0, br0, 1, 0, NNODES);
    k_scan<<<1, 1024>>>();
    k_scatter<<<(TE + 255) / 256, 256>>>(ei);

    k_gat<<<GAT_BLOCKS, 256>>>(att0, bias0, g0, be0, rm0, rv0);

    k_mm_tc<<<GEMM_BLOCKS, 256, SMEM_BYTES>>>(nullptr, 1, Wl1, bl1, Wr1, br1, 1, 0, NNODES);
    k_gat<<<GAT_BLOCKS, 256>>>(att1, bias1, g1, be1, rm1, rv1);

    k_mm_tc<<<GEMM_BLOCKS, 256, SMEM_BYTES>>>(nullptr, 1, Wlin1, blin1, nullptr, nullptr, 0, 1, NNODES);
    k_lin2<<<GAT_BLOCKS, 256>>>(Wlin2, blin2, out);
}